// round 7
// baseline (speedup 1.0000x reference)
#include <cuda_runtime.h>
#include <cuda_bf16.h>
#include <math.h>

// Problem constants
#define B_   16
#define T_   512
#define C_   8
#define S_   64
#define KSZ_ 32
#define TOUT_ 481   // T - KSZ + 1

// Scratch (no allocations allowed in kernel_launch)
__device__ float g_xmean[B_ * C_];
__device__ float g_xrstd[B_ * C_];
// Packed kernel constants, per k (KSZ index):
//   g_kq[k*512 + sp*16 + i*2 + half] = -2 * kern_norm[s = 2*sp + half][k][i]
__device__ __align__(16) float g_kq[KSZ_ * 32 * 16];   // 16384 floats
//   g_kc[k*64 + sp*2 + half] = sum_c kern_norm[s][k][c]^2
__device__ __align__(16) float g_kc[KSZ_ * S_];        // 2048 floats

// ---------------------------------------------------------------------------
__device__ __forceinline__ void warp_red2(float& a, float& b) {
    #pragma unroll
    for (int o = 16; o > 0; o >>= 1) {
        a += __shfl_xor_sync(0xffffffffu, a, o);
        b += __shfl_xor_sync(0xffffffffu, b, o);
    }
}

// ---------------------------------------------------------------------------
// Kernel 1: stats + kernel normalization/reorder. (unchanged, verified)
// ---------------------------------------------------------------------------
__global__ void lsd_stats_kernel(const float* __restrict__ x,
                                 const float* __restrict__ kern) {
    __shared__ float r1[8];
    __shared__ float r2[8];
    __shared__ float s_mean, s_rstd;
    int tid = threadIdx.x;
    int wid = tid >> 5;
    int lid = tid & 31;

    if (blockIdx.x < 128) {
        int b = blockIdx.x >> 3;
        int c = blockIdx.x & 7;
        const float* xp = x + (size_t)b * T_ * C_ + c;
        float v0 = xp[(size_t)tid * C_];
        float v1 = xp[(size_t)(tid + 256) * C_];
        float sum = v0 + v1;
        float sq  = v0 * v0 + v1 * v1;
        warp_red2(sum, sq);
        if (lid == 0) { r1[wid] = sum; r2[wid] = sq; }
        __syncthreads();
        if (wid == 0) {
            float a = (lid < 8) ? r1[lid] : 0.0f;
            float bq = (lid < 8) ? r2[lid] : 0.0f;
            #pragma unroll
            for (int o = 4; o > 0; o >>= 1) {
                a  += __shfl_xor_sync(0xffffffffu, a, o);
                bq += __shfl_xor_sync(0xffffffffu, bq, o);
            }
            if (lid == 0) {
                float mean = a * (1.0f / T_);
                float var  = bq * (1.0f / T_) - mean * mean;
                float std  = sqrtf(fmaxf(var, 0.0f)) + 1e-8f;
                g_xmean[b * C_ + c] = mean;
                g_xrstd[b * C_ + c] = 1.0f / std;
            }
        }
    } else {
        int s = blockIdx.x - 128;
        const float* kp = kern + (size_t)s * KSZ_ * C_;
        float v = kp[tid];
        float sum = v, sq = v * v;
        warp_red2(sum, sq);
        if (lid == 0) { r1[wid] = sum; r2[wid] = sq; }
        __syncthreads();
        if (tid == 0) {
            float a = 0.0f, bq = 0.0f;
            #pragma unroll
            for (int j = 0; j < 8; j++) { a += r1[j]; bq += r2[j]; }
            float mean = a * (1.0f / 256.0f);
            float var  = bq * (1.0f / 256.0f) - mean * mean;
            float std  = sqrtf(fmaxf(var, 0.0f)) + 1e-8f;
            s_mean = mean;
            s_rstd = 1.0f / std;
        }
        __syncthreads();

        float norm = (v - s_mean) * s_rstd;
        int k = tid >> 3;
        int c = tid & 7;
        int sp = s >> 1;
        int half = s & 1;
        g_kq[k * 512 + sp * 16 + c * 2 + half] = -2.0f * norm;

        float nsq = norm * norm;
        nsq += __shfl_down_sync(0xffffffffu, nsq, 4, 8);
        nsq += __shfl_down_sync(0xffffffffu, nsq, 2, 8);
        nsq += __shfl_down_sync(0xffffffffu, nsq, 1, 8);
        if (c == 0) g_kc[k * 64 + sp * 2 + half] = nsq;
    }
}

// ---------------------------------------------------------------------------
// Kernel 2: block = (1 k) x (256 t). 4 warps = {s-half, t-group}; each lane
// produces 4 consecutive t from an 11-sample register window; each warp does
// 16 sp (32 s). Grid: (32 k, 2 t-chunks, 16 b) = 1024 blocks of 128 threads,
// 7 blocks/SM -> whole grid co-resident in one wave.
// ---------------------------------------------------------------------------
__device__ __forceinline__ unsigned long long fma2(unsigned long long a,
                                                   unsigned long long b,
                                                   unsigned long long c) {
    unsigned long long d;
    asm("fma.rn.f32x2 %0, %1, %2, %3;" : "=l"(d) : "l"(a), "l"(b), "l"(c));
    return d;
}

#define SXP_IDX(v) ((v) + ((v) >> 2))   // skewed: stride-4 lane pattern -> stride-5

__global__ void __launch_bounds__(128, 7)
lsd_main_kernel(const float* __restrict__ x, float* __restrict__ out) {
    __shared__ float sxp[360];                        // skewed window (287 -> 358 used)
    __shared__ __align__(16) float skq[512];          // this k's packed table
    __shared__ __align__(16) float skc[64];           // this k's ||K||^2 pairs
    __shared__ float so[2][264];                      // per-s-half partial mins

    int tid = threadIdx.x;
    int ty  = tid >> 5;          // warp
    int h   = ty & 1;            // s-half (16 sp each)
    int tg  = ty >> 1;           // t-group (128 t each)
    int l   = tid & 31;          // lane
    int k   = blockIdx.x;
    int t0  = blockIdx.y << 8;   // 0 or 256
    int b   = blockIdx.z;

    int cx = k >> 2;
    int m  = k & 3;

    // --- stage x window (one channel), normalized, into skewed smem ---
    {
        float mean = g_xmean[b * C_ + cx];
        float rstd = g_xrstd[b * C_ + cx];
        #pragma unroll
        for (int rep = 0; rep < 3; rep++) {
            int j = tid + rep * 128;
            if (j < 287) {
                float v = 0.0f;
                int tgl = t0 + j;
                if (tgl < T_) v = (x[((size_t)b * T_ + tgl) * C_ + cx] - mean) * rstd;
                sxp[SXP_IDX(j)] = v;
            }
        }
    }
    // --- stage this k's kernel table ---
    {
        const float4* src = (const float4*)(g_kq + (size_t)k * 512);
        ((float4*)skq)[tid] = src[tid];
        if (tid < 16) ((float4*)skc)[tid] = ((const float4*)(g_kc + (size_t)k * 64))[tid];
    }
    __syncthreads();

    // --- per-lane register window: 11 packed {v,v} covering 4 patches ---
    int base = tg * 128 + l * 4 + m * 8;
    unsigned long long w2[11];
    float pn[4];
    #pragma unroll
    for (int v = 0; v < 11; v++) {
        float f = sxp[SXP_IDX(base + v)];
        unsigned int u = __float_as_uint(f);
        w2[v] = ((unsigned long long)u << 32) | u;
    }
    #pragma unroll
    for (int j = 0; j < 4; j++) {
        float acc = 0.0f;
        #pragma unroll
        for (int i = 0; i < 8; i++) {
            float f = __uint_as_float((unsigned int)w2[j + i]);
            acc = fmaf(f, f, acc);
        }
        pn[j] = acc;   // ||p||^2 for local t = tg*128 + l*4 + j
    }

    // --- main loop: this warp's 16 sp (32 s values) ---
    const ulonglong2* kq2 = (const ulonglong2*)skq;     // idx: sp*4 + q
    const unsigned long long* kcp = (const unsigned long long*)skc;

    float mn[4];
    #pragma unroll
    for (int j = 0; j < 4; j++) mn[j] = 3.402823466e38f;

    #pragma unroll
    for (int spq = 0; spq < 16; spq++) {
        int sp = (h << 4) + spq;
        ulonglong2 q0 = kq2[sp * 4 + 0];
        ulonglong2 q1 = kq2[sp * 4 + 1];
        ulonglong2 q2 = kq2[sp * 4 + 2];
        ulonglong2 q3 = kq2[sp * 4 + 3];
        unsigned long long c0 = kcp[sp];
        #pragma unroll
        for (int j = 0; j < 4; j++) {
            unsigned long long d = c0;
            d = fma2(w2[j + 0], q0.x, d);
            d = fma2(w2[j + 1], q0.y, d);
            d = fma2(w2[j + 2], q1.x, d);
            d = fma2(w2[j + 3], q1.y, d);
            d = fma2(w2[j + 4], q2.x, d);
            d = fma2(w2[j + 5], q2.y, d);
            d = fma2(w2[j + 6], q3.x, d);
            d = fma2(w2[j + 7], q3.y, d);
            float lo = __uint_as_float((unsigned int)d);
            float hi = __uint_as_float((unsigned int)(d >> 32));
            mn[j] = fminf(mn[j], fminf(lo, hi));
        }
    }

    // --- partial mins -> smem: so[h][tg*132 + j*33 + l] (conflict-free) ---
    #pragma unroll
    for (int j = 0; j < 4; j++) {
        so[h][tg * 132 + j * 33 + l] = pn[j] + mn[j];
    }
    __syncthreads();

    // --- combine 2 s-halves, store (2 t per thread) ---
    #pragma unroll
    for (int rep = 0; rep < 2; rep++) {
        int tt = tid + rep * 128;        // local t = tgr*128 + lr*4 + jr
        int t = t0 + tt;
        if (t < TOUT_) {
            int tgr = tt >> 7;
            int r   = tt & 127;
            int lr  = r >> 2;
            int jr  = r & 3;
            int idx = tgr * 132 + jr * 33 + lr;
            float v = fminf(so[0][idx], so[1][idx]);
            out[((size_t)b * TOUT_ + t) * KSZ_ + k] = v;
        }
    }
}

extern "C" void kernel_launch(void* const* d_in, const int* in_sizes, int n_in,
                              void* d_out, int out_size) {
    const float* x    = (const float*)d_in[0];   // (16, 512, 8)
    const float* kern = (const float*)d_in[1];   // (64, 32, 8)
    float* out = (float*)d_out;                  // (16, 481, 32)

    lsd_stats_kernel<<<192, 256>>>(x, kern);

    dim3 grid(32, 2, 16);   // (k, t-chunks, batch)
    lsd_main_kernel<<<grid, 128>>>(x, out);
}